// round 11
// baseline (speedup 1.0000x reference)
#include <cuda_runtime.h>
#include <cuda_fp16.h>
#include <cuda_bf16.h>
#include <math.h>
#include <stdint.h>

#define NTOK 3072
#define DIM  768
#define NHEAD 12
#define HDIM 64

// ---------------- static device scratch ----------------
__device__ unsigned short g_hab[NTOK * DIM];
__device__ unsigned short g_hsb[NTOK * DIM];
__device__ unsigned short g_Wca[2 * DIM * DIM];     // Wq_a | Wk_a  bf16
__device__ unsigned short g_Wcb[3 * DIM * DIM];     // Wq | Wk | Wv bf16
__device__ float g_bca[2 * DIM];                    // bq_a | bk_a
__device__ float g_bcb[3 * DIM];                    // bq | bk | bv
__device__ unsigned short g_qka[NTOK * 2 * DIM];    // qa | ka bf16 (ld 1536)
__device__ unsigned short g_QKV[NTOK * 3 * DIM];    // Q | K | V bf16 (ld 2304)
__device__ unsigned short g_Vt [DIM * NTOK];        // V^T bf16
__device__ float g_O [NTOK * DIM];
__device__ float g_S [(size_t)NTOK * NTOK];
__device__ unsigned short g_Att[(size_t)NTOK * NTOK];
__device__ unsigned short g_Shx[(size_t)NHEAD * NTOK * NTOK]; // fp16 exp planes
__device__ float g_Wf[(size_t)NTOK * NTOK];
__device__ float g_rsum[NHEAD * NTOK];
__device__ double g_stats[2];

// ---------------- helpers ----------------
__device__ __forceinline__ float warp_sum(float v) {
    #pragma unroll
    for (int o = 16; o; o >>= 1) v += __shfl_xor_sync(0xffffffffu, v, o);
    return v;
}
__device__ __forceinline__ void mma_bf16(float* d, const uint32_t* a, uint32_t b0, uint32_t b1) {
    asm volatile(
        "mma.sync.aligned.m16n8k16.row.col.f32.bf16.bf16.f32 "
        "{%0,%1,%2,%3}, {%4,%5,%6,%7}, {%8,%9}, {%0,%1,%2,%3};\n"
        : "+f"(d[0]), "+f"(d[1]), "+f"(d[2]), "+f"(d[3])
        : "r"(a[0]), "r"(a[1]), "r"(a[2]), "r"(a[3]), "r"(b0), "r"(b1));
}
__device__ __forceinline__ void ldsm_x4(uint32_t* r, uint32_t addr) {
    asm volatile("ldmatrix.sync.aligned.m8n8.x4.shared.b16 {%0,%1,%2,%3}, [%4];"
        : "=r"(r[0]), "=r"(r[1]), "=r"(r[2]), "=r"(r[3]) : "r"(addr));
}
__device__ __forceinline__ void cpa16(uint32_t smem, const void* gptr) {
    asm volatile("cp.async.ca.shared.global [%0], [%1], 16;\n" :: "r"(smem), "l"(gptr));
}
#define CP_COMMIT()  asm volatile("cp.async.commit_group;\n")
#define CP_WAIT(N)   asm volatile("cp.async.wait_group %0;\n" :: "n"(N))

#define RSTR 144        // bytes per smem row (128 data + 16 pad); conflict-free
#define NSTAGE 3

// ---------------- fp32 -> bf16 conversion, multi-array fused ----------------
__global__ void f2b_multi(const float4* a0, uint2* o0, int n0,
                          const float4* a1, uint2* o1, int n1,
                          const float4* a2, uint2* o2, int n2,
                          const float4* a3, uint2* o3, int n3)
{
    int i = blockIdx.x * blockDim.x + threadIdx.x;
    const float4* in; uint2* out; int idx;
    if (i < n0) { in = a0; out = o0; idx = i; }
    else if (i < n0 + n1) { in = a1; out = o1; idx = i - n0; }
    else if (i < n0 + n1 + n2) { in = a2; out = o2; idx = i - n0 - n1; }
    else if (i < n0 + n1 + n2 + n3) { in = a3; out = o3; idx = i - n0 - n1 - n2; }
    else return;
    float4 v = in[idx];
    __nv_bfloat162 a = __float22bfloat162_rn(make_float2(v.x, v.y));
    __nv_bfloat162 b = __float22bfloat162_rn(make_float2(v.z, v.w));
    uint2 u; u.x = *(uint32_t*)&a; u.y = *(uint32_t*)&b;
    out[idx] = u;
}

// ---------------- bias concat ----------------
__global__ void bcat_kernel(const float* a0, const float* a1, float* outA,
                            const float* b0, const float* b1, const float* b2, float* outB)
{
    int i = blockIdx.x * blockDim.x + threadIdx.x;
    if (i < DIM) {
        outA[i] = a0[i]; outA[DIM + i] = a1[i];
        outB[i] = b0[i]; outB[DIM + i] = b1[i]; outB[2 * DIM + i] = b2[i];
    }
}

// ================= bf16 TC NT GEMM (ldmatrix, BK=64, 3-stage): C = scale*A.B^T (+bias) =================
template <int BM, typename OutT>
__global__ __launch_bounds__(256, 2) void gemm_nt_bf(
    const unsigned short* __restrict__ A, int lda,
    const unsigned short* __restrict__ B, int ldb,
    OutT* __restrict__ C, int ldc, int K,
    const float* __restrict__ bias, float scale)
{
    constexpr int WMN = BM / 32;
    constexpr int WNN = 8 / WMN;
    constexpr int NI  = 128 / (WNN * 8);
    constexpr int NB  = NI / 2;
    constexpr int CA  = BM / 32;
    constexpr int CB  = 4;
    constexpr uint32_t stgA = BM * RSTR;
    constexpr uint32_t stgB = 128 * RSTR;

    extern __shared__ uint32_t dynsm[];
    const uint32_t sbase = (uint32_t)__cvta_generic_to_shared(dynsm);
    const uint32_t sA = sbase;
    const uint32_t sB = sbase + NSTAGE * stgA;

    const int tid = threadIdx.x;
    const int row0 = blockIdx.y * BM, col0 = blockIdx.x * 128;
    const int wid = tid >> 5, lane = tid & 31;
    const int wm = wid % WMN, wn = wid / WMN;
    const int g = lane >> 2, tig = lane & 3;
    const int seg = lane >> 3, l7 = lane & 7;

    float acc[2][NI][4];
    #pragma unroll
    for (int i = 0; i < 2; i++)
        #pragma unroll
        for (int j = 0; j < NI; j++)
            #pragma unroll
            for (int q = 0; q < 4; q++) acc[i][j][q] = 0.f;

    const unsigned short* gA[CA]; uint32_t dA[CA];
    #pragma unroll
    for (int t = 0; t < CA; t++) {
        int ch = tid + t * 256;
        int r = ch >> 3, c16 = ch & 7;
        gA[t] = A + (size_t)(row0 + r) * lda + c16 * 8;
        dA[t] = sA + r * RSTR + c16 * 16;
    }
    const unsigned short* gB[CB]; uint32_t dB[CB];
    #pragma unroll
    for (int t = 0; t < CB; t++) {
        int ch = tid + t * 256;
        int r = ch >> 3, c16 = ch & 7;
        gB[t] = B + (size_t)(col0 + r) * ldb + c16 * 8;
        dB[t] = sB + r * RSTR + c16 * 16;
    }

    const int rowA = (seg & 1) * 8 + l7;
    const uint32_t kAb = (seg >> 1) * 16;
    uint32_t aAddr[2];
    #pragma unroll
    for (int mi = 0; mi < 2; mi++)
        aAddr[mi] = sA + (uint32_t)(wm * 32 + mi * 16 + rowA) * RSTR + kAb;
    const int rowB = (seg >> 1) * 8 + l7;
    const uint32_t kBb = (seg & 1) * 16;
    uint32_t bAddr[NB];
    #pragma unroll
    for (int nb = 0; nb < NB; nb++)
        bAddr[nb] = sB + (uint32_t)(wn * (NI * 8) + nb * 16 + rowB) * RSTR + kBb;

    const int niter = K >> 6;

    #pragma unroll
    for (int s = 0; s < 2; s++) {
        const int k0 = s << 6;
        #pragma unroll
        for (int t = 0; t < CA; t++) cpa16(dA[t] + s * stgA, gA[t] + k0);
        #pragma unroll
        for (int t = 0; t < CB; t++) cpa16(dB[t] + s * stgB, gB[t] + k0);
        CP_COMMIT();
    }

    for (int it = 0; it < niter; ++it) {
        if (it + 2 < niter) {
            const int s = (it + 2) % NSTAGE;
            const int k0 = (it + 2) << 6;
            #pragma unroll
            for (int t = 0; t < CA; t++) cpa16(dA[t] + s * stgA, gA[t] + k0);
            #pragma unroll
            for (int t = 0; t < CB; t++) cpa16(dB[t] + s * stgB, gB[t] + k0);
            CP_COMMIT();
            CP_WAIT(2);
        } else if (it + 2 == niter) {
            CP_WAIT(1);
        } else {
            CP_WAIT(0);
        }
        __syncthreads();

        const int st = it % NSTAGE;
        const uint32_t aOff = st * stgA, bOff = st * stgB;
        #pragma unroll
        for (int ks = 0; ks < 4; ks++) {
            const uint32_t kadd = ks * 32;
            uint32_t af[2][4];
            ldsm_x4(af[0], aAddr[0] + aOff + kadd);
            ldsm_x4(af[1], aAddr[1] + aOff + kadd);
            #pragma unroll
            for (int nb = 0; nb < NB; nb++) {
                uint32_t bq[4];
                ldsm_x4(bq, bAddr[nb] + bOff + kadd);
                mma_bf16(acc[0][2 * nb    ], af[0], bq[0], bq[1]);
                mma_bf16(acc[1][2 * nb    ], af[1], bq[0], bq[1]);
                mma_bf16(acc[0][2 * nb + 1], af[0], bq[2], bq[3]);
                mma_bf16(acc[1][2 * nb + 1], af[1], bq[2], bq[3]);
            }
        }
        __syncthreads();
    }

    #pragma unroll
    for (int mi = 0; mi < 2; mi++) {
        #pragma unroll
        for (int gg = 0; gg < 2; gg++) {
            int r = row0 + wm * 32 + mi * 16 + g + gg * 8;
            #pragma unroll
            for (int ni = 0; ni < NI; ni++) {
                int c = col0 + wn * (NI * 8) + ni * 8 + tig * 2;
                float vx = acc[mi][ni][gg * 2 + 0] * scale;
                float vy = acc[mi][ni][gg * 2 + 1] * scale;
                if (bias) { vx += bias[c]; vy += bias[c + 1]; }
                if constexpr (sizeof(OutT) == 2) {
                    __nv_bfloat162 bv = __float22bfloat162_rn(make_float2(vx, vy));
                    *(uint32_t*)((unsigned short*)C + (size_t)r * ldc + c) = *(uint32_t*)&bv;
                } else {
                    float2 v; v.x = vx; v.y = vy;
                    *(float2*)((float*)C + (size_t)r * ldc + c) = v;
                }
            }
        }
    }
}

// ================= fused 12-head logits GEMM (BK=64: 1 stage per head) =================
__global__ __launch_bounds__(256, 2) void heads_gemm_bf(
    const unsigned short* __restrict__ A, int lda,
    const unsigned short* __restrict__ B, int ldb,
    unsigned short* __restrict__ P,
    float* __restrict__ rsum, int rowbase)
{
    constexpr uint32_t stgA = 128 * RSTR;
    constexpr uint32_t stgB = 128 * RSTR;

    extern __shared__ uint32_t dynsm[];
    const uint32_t sbase = (uint32_t)__cvta_generic_to_shared(dynsm);
    const uint32_t sA = sbase;
    const uint32_t sB = sbase + NSTAGE * stgA;

    const int tid = threadIdx.x;
    const int row0 = (rowbase + blockIdx.y) * 128, col0 = blockIdx.x * 128;
    const int wid = tid >> 5, lane = tid & 31;
    const int wm = wid & 3, wn = wid >> 2;
    const int g = lane >> 2, tig = lane & 3;
    const int seg = lane >> 3, l7 = lane & 7;

    const unsigned short* gA[4]; uint32_t dA[4];
    const unsigned short* gB[4]; uint32_t dB[4];
    #pragma unroll
    for (int t = 0; t < 4; t++) {
        int ch = tid + t * 256;
        int r = ch >> 3, c16 = ch & 7;
        gA[t] = A + (size_t)(row0 + r) * lda + c16 * 8;
        dA[t] = sA + r * RSTR + c16 * 16;
        gB[t] = B + (size_t)(col0 + r) * ldb + c16 * 8;
        dB[t] = sB + r * RSTR + c16 * 16;
    }

    const int rowA = (seg & 1) * 8 + l7;
    const uint32_t kAb = (seg >> 1) * 16;
    uint32_t aAddr[2];
    #pragma unroll
    for (int mi = 0; mi < 2; mi++)
        aAddr[mi] = sA + (uint32_t)(wm * 32 + mi * 16 + rowA) * RSTR + kAb;
    const int rowB = (seg >> 1) * 8 + l7;
    const uint32_t kBb = (seg & 1) * 16;
    uint32_t bAddr[4];
    #pragma unroll
    for (int nb = 0; nb < 4; nb++)
        bAddr[nb] = sB + (uint32_t)(wn * 64 + nb * 16 + rowB) * RSTR + kBb;

    #pragma unroll
    for (int s = 0; s < 2; s++) {
        const int k0 = s << 6;
        #pragma unroll
        for (int t = 0; t < 4; t++) {
            cpa16(dA[t] + s * stgA, gA[t] + k0);
            cpa16(dB[t] + s * stgB, gB[t] + k0);
        }
        CP_COMMIT();
    }

    for (int h = 0; h < NHEAD; h++) {
        if (h + 2 < NHEAD) {
            const int s = (h + 2) % NSTAGE;
            const int k0 = (h + 2) << 6;
            #pragma unroll
            for (int t = 0; t < 4; t++) {
                cpa16(dA[t] + s * stgA, gA[t] + k0);
                cpa16(dB[t] + s * stgB, gB[t] + k0);
            }
            CP_COMMIT();
            CP_WAIT(2);
        } else if (h + 2 == NHEAD) {
            CP_WAIT(1);
        } else {
            CP_WAIT(0);
        }
        __syncthreads();

        float acc[2][8][4];
        #pragma unroll
        for (int i = 0; i < 2; i++)
            #pragma unroll
            for (int j = 0; j < 8; j++)
                #pragma unroll
                for (int q = 0; q < 4; q++) acc[i][j][q] = 0.f;

        const int st = h % NSTAGE;
        const uint32_t aOff = st * stgA, bOff = st * stgB;
        #pragma unroll
        for (int ks = 0; ks < 4; ks++) {
            const uint32_t kadd = ks * 32;
            uint32_t af[2][4];
            ldsm_x4(af[0], aAddr[0] + aOff + kadd);
            ldsm_x4(af[1], aAddr[1] + aOff + kadd);
            #pragma unroll
            for (int nb = 0; nb < 4; nb++) {
                uint32_t bq[4];
                ldsm_x4(bq, bAddr[nb] + bOff + kadd);
                mma_bf16(acc[0][2 * nb    ], af[0], bq[0], bq[1]);
                mma_bf16(acc[1][2 * nb    ], af[1], bq[0], bq[1]);
                mma_bf16(acc[0][2 * nb + 1], af[0], bq[2], bq[3]);
                mma_bf16(acc[1][2 * nb + 1], af[1], bq[2], bq[3]);
            }
        }
        __syncthreads();

        __half* plane = (__half*)P + (size_t)h * NTOK * NTOK;
        float* rs_h = rsum + h * NTOK;
        #pragma unroll
        for (int mi = 0; mi < 2; mi++) {
            #pragma unroll
            for (int gg = 0; gg < 2; gg++) {
                int r = row0 + wm * 32 + mi * 16 + g + gg * 8;
                float rowacc = 0.f;
                #pragma unroll
                for (int ni = 0; ni < 8; ni++) {
                    int c = col0 + wn * 64 + ni * 8 + tig * 2;
                    float e0 = __expf(0.125f * acc[mi][ni][gg * 2 + 0]);
                    float e1 = __expf(0.125f * acc[mi][ni][gg * 2 + 1]);
                    *(__half2*)(plane + (size_t)r * NTOK + c) = __floats2half2_rn(e0, e1);
                    rowacc += e0 + e1;
                }
                rowacc += __shfl_xor_sync(0xffffffffu, rowacc, 1);
                rowacc += __shfl_xor_sync(0xffffffffu, rowacc, 2);
                if (tig == 0) atomicAdd(&rs_h[r], rowacc);
            }
        }
    }
}

// ================= V transpose (bf16, strided input) =================
__global__ void transpose_v(const unsigned short* __restrict__ V, int ldv,
                            unsigned short* __restrict__ Vt)
{
    __shared__ unsigned short t[32][34];
    int x = blockIdx.x * 32 + threadIdx.x;
    int y0 = blockIdx.y * 32;
    for (int dy = threadIdx.y; dy < 32; dy += 8)
        t[dy][threadIdx.x] = V[(size_t)(y0 + dy) * ldv + x];
    __syncthreads();
    int xo = blockIdx.y * 32 + threadIdx.x;
    int yo0 = blockIdx.x * 32;
    for (int dy = threadIdx.y; dy < 32; dy += 8)
        Vt[(size_t)(yo0 + dy) * NTOK + xo] = t[threadIdx.x][dy];
}

// ================= zero rsum + stats =================
__global__ void zero_kernel(float* __restrict__ rsum)
{
    int i = blockIdx.x * blockDim.x + threadIdx.x;
    if (i < NHEAD * NTOK) rsum[i] = 0.f;
    if (i == 0) { g_stats[0] = 0.0; g_stats[1] = 0.0; }
}

// ================= combine: Wa avg + Gaussian + stats (row-group) =================
__global__ __launch_bounds__(384) void wf_combine_kernel(
    const float* __restrict__ dd, const float* __restrict__ rsum, int row_off)
{
    __shared__ float shInv[NHEAD];
    __shared__ float redA[12], redB[12];
    const int i = row_off + blockIdx.x, tid = threadIdx.x;
    const int lane = tid & 31, wid = tid >> 5;
    const int NP8 = NTOK / 8;
    const size_t PL8 = (size_t)NTOK * NTOK / 8;
    const uint4* planes = (const uint4*)g_Shx;
    const size_t rowoff = (size_t)i * NP8;

    if (tid < NHEAD) shInv[tid] = 1.f / (rsum[tid * NTOK + i] * (float)NHEAD);
    __syncthreads();

    float iz[NHEAD];
    #pragma unroll
    for (int h = 0; h < NHEAD; h++) iz[h] = shInv[h];

    const float4* drow = (const float4*)(dd + (size_t)i * NTOK);
    float4* frow = (float4*)(g_Wf + (size_t)i * NTOK);
    float s1 = 0.f, s2 = 0.f;

    const int j = tid;
    {
        float wa[8];
        #pragma unroll
        for (int q = 0; q < 8; q++) wa[q] = 0.f;
        #pragma unroll
        for (int h = 0; h < NHEAD; h++) {
            uint4 u = planes[h * PL8 + rowoff + j];
            float2 e0 = __half22float2(*(__half2*)&u.x);
            float2 e1 = __half22float2(*(__half2*)&u.y);
            float2 e2 = __half22float2(*(__half2*)&u.z);
            float2 e3 = __half22float2(*(__half2*)&u.w);
            wa[0] += e0.x * iz[h]; wa[1] += e0.y * iz[h];
            wa[2] += e1.x * iz[h]; wa[3] += e1.y * iz[h];
            wa[4] += e2.x * iz[h]; wa[5] += e2.y * iz[h];
            wa[6] += e3.x * iz[h]; wa[7] += e3.y * iz[h];
        }
        float4 d0 = drow[j * 2], d1 = drow[j * 2 + 1];
        float df[8] = {d0.x, d0.y, d0.z, d0.w, d1.x, d1.y, d1.z, d1.w};
        float wf[8];
        #pragma unroll
        for (int q = 0; q < 8; q++) {
            wf[q] = __expf(-0.5f * df[q] * df[q]) * wa[q];
            s1 += wf[q];
            s2 += wf[q] * wf[q];
        }
        float4 w0, w1;
        w0.x = wf[0]; w0.y = wf[1]; w0.z = wf[2]; w0.w = wf[3];
        w1.x = wf[4]; w1.y = wf[5]; w1.z = wf[6]; w1.w = wf[7];
        frow[j * 2] = w0;
        frow[j * 2 + 1] = w1;
    }

    s1 = warp_sum(s1);
    s2 = warp_sum(s2);
    if (lane == 0) { redA[wid] = s1; redB[wid] = s2; }
    __syncthreads();
    if (wid == 0) {
        float a = (lane < 12) ? redA[lane] : 0.f;
        float b = (lane < 12) ? redB[lane] : 0.f;
        a = warp_sum(a);
        b = warp_sum(b);
        if (lane == 0) {
            atomicAdd(&g_stats[0], (double)a);
            atomicAdd(&g_stats[1], (double)b);
        }
    }
}

// ================= masked softmax (no shift) -> bf16 attn =================
__global__ __launch_bounds__(256) void masked_softmax_kernel()
{
    __shared__ float4 z[NTOK / 4];
    __shared__ float redB[8];
    __shared__ float sh_thr;
    const int i = blockIdx.x, tid = threadIdx.x;
    const int lane = tid & 31, wid = tid >> 5;

    if (tid == 0) {
        double cnt = (double)NTOK * (double)NTOK;
        double mean = g_stats[0] / cnt;
        double var = (g_stats[1] - g_stats[0] * g_stats[0] / cnt) / (cnt - 1.0);
        if (var < 0.0) var = 0.0;
        sh_thr = (float)(mean + 0.5 * sqrt(var));
    }
    __syncthreads();
    const float thr = sh_thr;
    const float invthr = 1.f / thr;

    const float4* srow = (const float4*)(g_S + (size_t)i * NTOK);
    const float4* frow = (const float4*)(g_Wf + (size_t)i * NTOK);

    float lsum = 0.f;
    #pragma unroll
    for (int t = 0; t < 3; t++) {
        int j = tid + t * 256;
        float4 wf = frow[j];
        float4 s = srow[j];
        float w0 = (wf.x < thr) ? wf.x * invthr : 1.f;
        float w1 = (wf.y < thr) ? wf.y * invthr : 1.f;
        float w2 = (wf.z < thr) ? wf.z * invthr : 1.f;
        float w3 = (wf.w < thr) ? wf.w * invthr : 1.f;
        float4 e;
        e.x = __expf(s.x * w0);
        e.y = __expf(s.y * w1);
        e.z = __expf(s.z * w2);
        e.w = __expf(s.w * w3);
        z[j] = e;
        lsum += e.x + e.y + e.z + e.w;
    }
    lsum = warp_sum(lsum);
    if (lane == 0) redB[wid] = lsum;
    __syncthreads();
    if (wid == 0) {
        float t = (lane < 8) ? redB[lane] : 0.f;
        t = warp_sum(t);
        if (lane == 0) redB[0] = t;
    }
    __syncthreads();
    const float invs = 1.f / redB[0];

    uint2* arow = (uint2*)((unsigned short*)g_Att + (size_t)i * NTOK);
    #pragma unroll
    for (int t = 0; t < 3; t++) {
        int j = tid + t * 256;
        float4 e = z[j];
        __nv_bfloat162 b0 = __float22bfloat162_rn(make_float2(e.x * invs, e.y * invs));
        __nv_bfloat162 b1 = __float22bfloat162_rn(make_float2(e.z * invs, e.w * invs));
        uint2 u; u.x = *(uint32_t*)&b0; u.y = *(uint32_t*)&b1;
        arow[j] = u;
    }
}

// ================= residual + LayerNorm =================
__global__ __launch_bounds__(256) void ln_kernel(
    const float* __restrict__ hs,
    const float* __restrict__ gamma,
    const float* __restrict__ beta,
    float* __restrict__ out)
{
    const int i = blockIdx.x, tid = threadIdx.x;
    const int lane = tid & 31, wid = tid >> 5;
    __shared__ float r1[8], r2[8];

    const float* orow = g_O + (size_t)i * DIM;
    const float* srow = hs + (size_t)i * DIM;

    float x[3];
    float s = 0.f, ss = 0.f;
    #pragma unroll
    for (int t = 0; t < 3; t++) {
        int c = tid + t * 256;
        x[t] = srow[c] + orow[c];
        s += x[t];
        ss += x[t] * x[t];
    }
    s = warp_sum(s);
    ss = warp_sum(ss);
    if (lane == 0) { r1[wid] = s; r2[wid] = ss; }
    __syncthreads();
    if (wid == 0) {
        float a = (lane < 8) ? r1[lane] : 0.f;
        float b = (lane < 8) ? r2[lane] : 0.f;
        a = warp_sum(a);
        b = warp_sum(b);
        if (lane == 0) { r1[0] = a; r2[0] = b; }
    }
    __syncthreads();
    const float mu = r1[0] * (1.f / DIM);
    const float var = r2[0] * (1.f / DIM) - mu * mu;
    const float inv = rsqrtf(var + 1e-5f);

    #pragma unroll
    for (int t = 0; t < 3; t++) {
        int c = tid + t * 256;
        out[(size_t)i * DIM + c] = (x[t] - mu) * inv * gamma[c] + beta[c];
    }
}

// ================= host =================
extern "C" void kernel_launch(void* const* d_in, const int* in_sizes, int n_in,
                              void* d_out, int out_size)
{
    const float* h_a  = (const float*)d_in[0];
    const float* h_s  = (const float*)d_in[1];
    const float* dep  = (const float*)d_in[2];
    const float* Wq_a = (const float*)d_in[3];
    const float* bq_a = (const float*)d_in[4];
    const float* Wk_a = (const float*)d_in[5];
    const float* bk_a = (const float*)d_in[6];
    const float* Wq   = (const float*)d_in[7];
    const float* bq   = (const float*)d_in[8];
    const float* Wk   = (const float*)d_in[9];
    const float* bk   = (const float*)d_in[10];
    const float* Wv   = (const float*)d_in[11];
    const float* bv   = (const float*)d_in[12];
    const float* lng  = (const float*)d_in[13];
    const float* lnb  = (const float*)d_in[14];
    float* out = (float*)d_out;

    unsigned short *hab, *hsb, *Wca, *Wcb, *qka, *QKV, *Vt, *Att, *Shx;
    float *bca, *bcb, *O, *S, *Wf, *rsum;
    cudaGetSymbolAddress((void**)&hab,  g_hab);
    cudaGetSymbolAddress((void**)&hsb,  g_hsb);
    cudaGetSymbolAddress((void**)&Wca,  g_Wca);
    cudaGetSymbolAddress((void**)&Wcb,  g_Wcb);
    cudaGetSymbolAddress((void**)&bca,  g_bca);
    cudaGetSymbolAddress((void**)&bcb,  g_bcb);
    cudaGetSymbolAddress((void**)&qka,  g_qka);
    cudaGetSymbolAddress((void**)&QKV,  g_QKV);
    cudaGetSymbolAddress((void**)&Vt,   g_Vt);
    cudaGetSymbolAddress((void**)&Att,  g_Att);
    cudaGetSymbolAddress((void**)&Shx,  g_Shx);
    cudaGetSymbolAddress((void**)&O,    g_O);
    cudaGetSymbolAddress((void**)&S,    g_S);
    cudaGetSymbolAddress((void**)&Wf,   g_Wf);
    cudaGetSymbolAddress((void**)&rsum, g_rsum);

    const int SM128 = NSTAGE * (128 * RSTR) * 2;               // 110592
    const int SM64  = NSTAGE * (64 * RSTR + 128 * RSTR);       // 82944

    static cudaStream_t s1;
    static cudaEvent_t e0, e1;
    static int inited = 0;
    if (!inited) {
        cudaStreamCreateWithFlags(&s1, cudaStreamNonBlocking);
        cudaEventCreateWithFlags(&e0, cudaEventDisableTiming);
        cudaEventCreateWithFlags(&e1, cudaEventDisableTiming);
        cudaFuncSetAttribute(gemm_nt_bf<64, unsigned short>,
                             cudaFuncAttributeMaxDynamicSharedMemorySize, SM64);
        cudaFuncSetAttribute(gemm_nt_bf<128, float>,
                             cudaFuncAttributeMaxDynamicSharedMemorySize, SM128);
        cudaFuncSetAttribute(gemm_nt_bf<64, float>,
                             cudaFuncAttributeMaxDynamicSharedMemorySize, SM64);
        cudaFuncSetAttribute(heads_gemm_bf,
                             cudaFuncAttributeMaxDynamicSharedMemorySize, SM128);
        inited = 1;
    }

    const dim3 blk(256);
    const dim3 gProjA(2 * DIM / 128, NTOK / 64);   // 12 x 48: qa|ka fused
    const dim3 gProjB(3 * DIM / 128, NTOK / 64);   // 18 x 48: Q|K|V fused
    const dim3 gNN(NTOK / 128, NTOK / 128);        // 24 x 24 (scores)
    const dim3 gHeadsGrp(NTOK / 128, 6);           // 24 x 6 per row-group
    const dim3 gAV(DIM / 128, NTOK / 64);          // 6 x 48
    const int NH4 = (NTOK * DIM) / 4;
    const int NW4 = (DIM * DIM) / 4;

    // biases concat before fork (ordered for both chains)
    bcat_kernel<<<3, 256>>>(bq_a, bk_a, bca, bq, bk, bv, bcb);

    cudaEventRecord(e0, 0);
    cudaStreamWaitEvent(s1, e0, 0);

    // ---- chain A (s1): structural attention weights ----
    zero_kernel<<<(NHEAD * NTOK + 255) / 256, 256, 0, s1>>>(rsum);
    f2b_multi<<<(NH4 + 2 * NW4 + 255) / 256, 256, 0, s1>>>(
        (const float4*)h_a, (uint2*)hab, NH4,
        (const float4*)Wq_a, (uint2*)Wca, NW4,
        (const float4*)Wk_a, (uint2*)(Wca + DIM * DIM), NW4,
        nullptr, nullptr, 0);
    gemm_nt_bf<64, unsigned short><<<gProjA, blk, SM64, s1>>>(
        hab, DIM, Wca, DIM, qka, 2 * DIM, DIM, bca, 1.f);
    // heads + combine interleaved in 4 row-groups (planes stay L2-hot)
    for (int gp = 0; gp < 4; gp++) {
        heads_gemm_bf<<<gHeadsGrp, blk, SM128, s1>>>(
            qka, 2 * DIM, qka + DIM, 2 * DIM, Shx, rsum, gp * 6);
        wf_combine_kernel<<<768, 384, 0, s1>>>(dep, rsum, gp * 768);
    }
    cudaEventRecord(e1, s1);

    // ---- chain B (default): guided attention ----
    f2b_multi<<<(NH4 + 3 * NW4 + 255) / 256, 256>>>(
        (const float4*)h_s, (uint2*)hsb, NH4,
        (const float4*)Wq, (uint2*)Wcb, NW4,
        (const float4*)Wk, (uint2*)(Wcb + DIM * DIM), NW4,
        (const float4*)Wv, (uint2*)(Wcb + 2 * DIM * DIM), NW4);
    gemm_nt_bf<64, unsigned short><<<gProjB, blk, SM64>>>(
        hsb, DIM, Wcb, DIM, QKV, 3 * DIM, DIM, bcb, 1.f);
    transpose_v<<<dim3(DIM / 32, NTOK / 32), dim3(32, 8)>>>(QKV + 2 * DIM, 3 * DIM, Vt);
    const float score_scale = 1.f / sqrtf((float)DIM);
    gemm_nt_bf<128, float><<<gNN, blk, SM128>>>(
        QKV, 3 * DIM, QKV + DIM, 3 * DIM, S, NTOK, DIM, nullptr, score_scale);

    // join, then tail
    cudaStreamWaitEvent(0, e1, 0);
    masked_softmax_kernel<<<NTOK, 256>>>();
    gemm_nt_bf<64, float><<<gAV, blk, SM64>>>(Att, NTOK, Vt, NTOK, O, DIM, NTOK, nullptr, 1.f);
    ln_kernel<<<NTOK, 256>>>(h_s, lng, lnb, out);
}

// round 12
// speedup vs baseline: 1.0289x; 1.0289x over previous
#include <cuda_runtime.h>
#include <cuda_fp16.h>
#include <cuda_bf16.h>
#include <math.h>
#include <stdint.h>

#define NTOK 3072
#define DIM  768
#define NHEAD 12
#define HDIM 64

// ---------------- static device scratch ----------------
__device__ unsigned short g_hab[NTOK * DIM];
__device__ unsigned short g_hsb[NTOK * DIM];
__device__ unsigned short g_Wca[2 * DIM * DIM];     // Wq_a | Wk_a  bf16
__device__ unsigned short g_Wcb[3 * DIM * DIM];     // Wq | Wk | Wv bf16
__device__ float g_bca[2 * DIM];
__device__ float g_bcb[3 * DIM];
__device__ unsigned short g_qka[NTOK * 2 * DIM];    // qa | ka bf16 (ld 1536)
__device__ unsigned short g_QKV[NTOK * 3 * DIM];    // Q | K | V bf16 (ld 2304)
__device__ unsigned short g_Vt [DIM * NTOK];        // V^T bf16
__device__ float g_O [NTOK * DIM];
__device__ float g_S [(size_t)NTOK * NTOK];
__device__ unsigned short g_Att[(size_t)NTOK * NTOK];
__device__ unsigned short g_Shx[(size_t)NHEAD * NTOK * NTOK]; // fp16 exp planes
__device__ float g_Wf[(size_t)NTOK * NTOK];
__device__ float g_rsum[NHEAD * NTOK];
__device__ double g_stats[2];

// ---------------- helpers ----------------
__device__ __forceinline__ float warp_sum(float v) {
    #pragma unroll
    for (int o = 16; o; o >>= 1) v += __shfl_xor_sync(0xffffffffu, v, o);
    return v;
}
__device__ __forceinline__ void mma_bf16(float* d, const uint32_t* a, uint32_t b0, uint32_t b1) {
    asm volatile(
        "mma.sync.aligned.m16n8k16.row.col.f32.bf16.bf16.f32 "
        "{%0,%1,%2,%3}, {%4,%5,%6,%7}, {%8,%9}, {%0,%1,%2,%3};\n"
        : "+f"(d[0]), "+f"(d[1]), "+f"(d[2]), "+f"(d[3])
        : "r"(a[0]), "r"(a[1]), "r"(a[2]), "r"(a[3]), "r"(b0), "r"(b1));
}
__device__ __forceinline__ void ldsm_x4(uint32_t* r, uint32_t addr) {
    asm volatile("ldmatrix.sync.aligned.m8n8.x4.shared.b16 {%0,%1,%2,%3}, [%4];"
        : "=r"(r[0]), "=r"(r[1]), "=r"(r[2]), "=r"(r[3]) : "r"(addr));
}
__device__ __forceinline__ void cpa16(uint32_t smem, const void* gptr) {
    asm volatile("cp.async.ca.shared.global [%0], [%1], 16;\n" :: "r"(smem), "l"(gptr));
}
#define CP_COMMIT()  asm volatile("cp.async.commit_group;\n")
#define CP_WAIT(N)   asm volatile("cp.async.wait_group %0;\n" :: "n"(N))

#define RSTR 144        // bytes per smem row (128 data + 16 pad); conflict-free
#define NSTAGE 3

// ---------------- fp32 -> bf16 conversion, multi-array fused ----------------
__global__ void f2b_multi(const float4* a0, uint2* o0, int n0,
                          const float4* a1, uint2* o1, int n1,
                          const float4* a2, uint2* o2, int n2,
                          const float4* a3, uint2* o3, int n3)
{
    int i = blockIdx.x * blockDim.x + threadIdx.x;
    const float4* in; uint2* out; int idx;
    if (i < n0) { in = a0; out = o0; idx = i; }
    else if (i < n0 + n1) { in = a1; out = o1; idx = i - n0; }
    else if (i < n0 + n1 + n2) { in = a2; out = o2; idx = i - n0 - n1; }
    else if (i < n0 + n1 + n2 + n3) { in = a3; out = o3; idx = i - n0 - n1 - n2; }
    else return;
    float4 v = in[idx];
    __nv_bfloat162 a = __float22bfloat162_rn(make_float2(v.x, v.y));
    __nv_bfloat162 b = __float22bfloat162_rn(make_float2(v.z, v.w));
    uint2 u; u.x = *(uint32_t*)&a; u.y = *(uint32_t*)&b;
    out[idx] = u;
}

// ---------------- bias concat ----------------
__global__ void bcat_kernel(const float* a0, const float* a1, float* outA,
                            const float* b0, const float* b1, const float* b2, float* outB)
{
    int i = blockIdx.x * blockDim.x + threadIdx.x;
    if (i < DIM) {
        outA[i] = a0[i]; outA[DIM + i] = a1[i];
        outB[i] = b0[i]; outB[DIM + i] = b1[i]; outB[2 * DIM + i] = b2[i];
    }
}

// ================= bf16 TC NT GEMM (ldmatrix, BK=64, 3-stage): C = scale*A.B^T (+bias) =================
template <int BM, typename OutT>
__global__ __launch_bounds__(256, 2) void gemm_nt_bf(
    const unsigned short* __restrict__ A, int lda,
    const unsigned short* __restrict__ B, int ldb,
    OutT* __restrict__ C, int ldc, int K,
    const float* __restrict__ bias, float scale)
{
    constexpr int WMN = BM / 32;
    constexpr int WNN = 8 / WMN;
    constexpr int NI  = 128 / (WNN * 8);
    constexpr int NB  = NI / 2;
    constexpr int CA  = BM / 32;
    constexpr int CB  = 4;
    constexpr uint32_t stgA = BM * RSTR;
    constexpr uint32_t stgB = 128 * RSTR;

    extern __shared__ uint32_t dynsm[];
    const uint32_t sbase = (uint32_t)__cvta_generic_to_shared(dynsm);
    const uint32_t sA = sbase;
    const uint32_t sB = sbase + NSTAGE * stgA;

    const int tid = threadIdx.x;
    const int row0 = blockIdx.y * BM, col0 = blockIdx.x * 128;
    const int wid = tid >> 5, lane = tid & 31;
    const int wm = wid % WMN, wn = wid / WMN;
    const int g = lane >> 2, tig = lane & 3;
    const int seg = lane >> 3, l7 = lane & 7;

    float acc[2][NI][4];
    #pragma unroll
    for (int i = 0; i < 2; i++)
        #pragma unroll
        for (int j = 0; j < NI; j++)
            #pragma unroll
            for (int q = 0; q < 4; q++) acc[i][j][q] = 0.f;

    const unsigned short* gA[CA]; uint32_t dA[CA];
    #pragma unroll
    for (int t = 0; t < CA; t++) {
        int ch = tid + t * 256;
        int r = ch >> 3, c16 = ch & 7;
        gA[t] = A + (size_t)(row0 + r) * lda + c16 * 8;
        dA[t] = sA + r * RSTR + c16 * 16;
    }
    const unsigned short* gB[CB]; uint32_t dB[CB];
    #pragma unroll
    for (int t = 0; t < CB; t++) {
        int ch = tid + t * 256;
        int r = ch >> 3, c16 = ch & 7;
        gB[t] = B + (size_t)(col0 + r) * ldb + c16 * 8;
        dB[t] = sB + r * RSTR + c16 * 16;
    }

    const int rowA = (seg & 1) * 8 + l7;
    const uint32_t kAb = (seg >> 1) * 16;
    uint32_t aAddr[2];
    #pragma unroll
    for (int mi = 0; mi < 2; mi++)
        aAddr[mi] = sA + (uint32_t)(wm * 32 + mi * 16 + rowA) * RSTR + kAb;
    const int rowB = (seg >> 1) * 8 + l7;
    const uint32_t kBb = (seg & 1) * 16;
    uint32_t bAddr[NB];
    #pragma unroll
    for (int nb = 0; nb < NB; nb++)
        bAddr[nb] = sB + (uint32_t)(wn * (NI * 8) + nb * 16 + rowB) * RSTR + kBb;

    const int niter = K >> 6;

    #pragma unroll
    for (int s = 0; s < 2; s++) {
        const int k0 = s << 6;
        #pragma unroll
        for (int t = 0; t < CA; t++) cpa16(dA[t] + s * stgA, gA[t] + k0);
        #pragma unroll
        for (int t = 0; t < CB; t++) cpa16(dB[t] + s * stgB, gB[t] + k0);
        CP_COMMIT();
    }

    for (int it = 0; it < niter; ++it) {
        if (it + 2 < niter) {
            const int s = (it + 2) % NSTAGE;
            const int k0 = (it + 2) << 6;
            #pragma unroll
            for (int t = 0; t < CA; t++) cpa16(dA[t] + s * stgA, gA[t] + k0);
            #pragma unroll
            for (int t = 0; t < CB; t++) cpa16(dB[t] + s * stgB, gB[t] + k0);
            CP_COMMIT();
            CP_WAIT(2);
        } else if (it + 2 == niter) {
            CP_WAIT(1);
        } else {
            CP_WAIT(0);
        }
        __syncthreads();

        const int st = it % NSTAGE;
        const uint32_t aOff = st * stgA, bOff = st * stgB;
        #pragma unroll
        for (int ks = 0; ks < 4; ks++) {
            const uint32_t kadd = ks * 32;
            uint32_t af[2][4];
            ldsm_x4(af[0], aAddr[0] + aOff + kadd);
            ldsm_x4(af[1], aAddr[1] + aOff + kadd);
            #pragma unroll
            for (int nb = 0; nb < NB; nb++) {
                uint32_t bq[4];
                ldsm_x4(bq, bAddr[nb] + bOff + kadd);
                mma_bf16(acc[0][2 * nb    ], af[0], bq[0], bq[1]);
                mma_bf16(acc[1][2 * nb    ], af[1], bq[0], bq[1]);
                mma_bf16(acc[0][2 * nb + 1], af[0], bq[2], bq[3]);
                mma_bf16(acc[1][2 * nb + 1], af[1], bq[2], bq[3]);
            }
        }
        __syncthreads();
    }

    #pragma unroll
    for (int mi = 0; mi < 2; mi++) {
        #pragma unroll
        for (int gg = 0; gg < 2; gg++) {
            int r = row0 + wm * 32 + mi * 16 + g + gg * 8;
            #pragma unroll
            for (int ni = 0; ni < NI; ni++) {
                int c = col0 + wn * (NI * 8) + ni * 8 + tig * 2;
                float vx = acc[mi][ni][gg * 2 + 0] * scale;
                float vy = acc[mi][ni][gg * 2 + 1] * scale;
                if (bias) { vx += bias[c]; vy += bias[c + 1]; }
                if constexpr (sizeof(OutT) == 2) {
                    __nv_bfloat162 bv = __float22bfloat162_rn(make_float2(vx, vy));
                    *(uint32_t*)((unsigned short*)C + (size_t)r * ldc + c) = *(uint32_t*)&bv;
                } else {
                    float2 v; v.x = vx; v.y = vy;
                    *(float2*)((float*)C + (size_t)r * ldc + c) = v;
                }
            }
        }
    }
}

// ================= fused 12-head logits GEMM (BK=64: 1 stage per head) =================
__global__ __launch_bounds__(256, 2) void heads_gemm_bf(
    const unsigned short* __restrict__ A, int lda,
    const unsigned short* __restrict__ B, int ldb,
    unsigned short* __restrict__ P,
    float* __restrict__ rsum, int rowbase)
{
    constexpr uint32_t stgA = 128 * RSTR;
    constexpr uint32_t stgB = 128 * RSTR;

    extern __shared__ uint32_t dynsm[];
    const uint32_t sbase = (uint32_t)__cvta_generic_to_shared(dynsm);
    const uint32_t sA = sbase;
    const uint32_t sB = sbase + NSTAGE * stgA;

    const int tid = threadIdx.x;
    const int row0 = (rowbase + blockIdx.y) * 128, col0 = blockIdx.x * 128;
    const int wid = tid >> 5, lane = tid & 31;
    const int wm = wid & 3, wn = wid >> 2;
    const int g = lane >> 2, tig = lane & 3;
    const int seg = lane >> 3, l7 = lane & 7;

    const unsigned short* gA[4]; uint32_t dA[4];
    const unsigned short* gB[4]; uint32_t dB[4];
    #pragma unroll
    for (int t = 0; t < 4; t++) {
        int ch = tid + t * 256;
        int r = ch >> 3, c16 = ch & 7;
        gA[t] = A + (size_t)(row0 + r) * lda + c16 * 8;
        dA[t] = sA + r * RSTR + c16 * 16;
        gB[t] = B + (size_t)(col0 + r) * ldb + c16 * 8;
        dB[t] = sB + r * RSTR + c16 * 16;
    }

    const int rowA = (seg & 1) * 8 + l7;
    const uint32_t kAb = (seg >> 1) * 16;
    uint32_t aAddr[2];
    #pragma unroll
    for (int mi = 0; mi < 2; mi++)
        aAddr[mi] = sA + (uint32_t)(wm * 32 + mi * 16 + rowA) * RSTR + kAb;
    const int rowB = (seg >> 1) * 8 + l7;
    const uint32_t kBb = (seg & 1) * 16;
    uint32_t bAddr[4];
    #pragma unroll
    for (int nb = 0; nb < 4; nb++)
        bAddr[nb] = sB + (uint32_t)(wn * 64 + nb * 16 + rowB) * RSTR + kBb;

    #pragma unroll
    for (int s = 0; s < 2; s++) {
        const int k0 = s << 6;
        #pragma unroll
        for (int t = 0; t < 4; t++) {
            cpa16(dA[t] + s * stgA, gA[t] + k0);
            cpa16(dB[t] + s * stgB, gB[t] + k0);
        }
        CP_COMMIT();
    }

    for (int h = 0; h < NHEAD; h++) {
        if (h + 2 < NHEAD) {
            const int s = (h + 2) % NSTAGE;
            const int k0 = (h + 2) << 6;
            #pragma unroll
            for (int t = 0; t < 4; t++) {
                cpa16(dA[t] + s * stgA, gA[t] + k0);
                cpa16(dB[t] + s * stgB, gB[t] + k0);
            }
            CP_COMMIT();
            CP_WAIT(2);
        } else if (h + 2 == NHEAD) {
            CP_WAIT(1);
        } else {
            CP_WAIT(0);
        }
        __syncthreads();

        float acc[2][8][4];
        #pragma unroll
        for (int i = 0; i < 2; i++)
            #pragma unroll
            for (int j = 0; j < 8; j++)
                #pragma unroll
                for (int q = 0; q < 4; q++) acc[i][j][q] = 0.f;

        const int st = h % NSTAGE;
        const uint32_t aOff = st * stgA, bOff = st * stgB;
        #pragma unroll
        for (int ks = 0; ks < 4; ks++) {
            const uint32_t kadd = ks * 32;
            uint32_t af[2][4];
            ldsm_x4(af[0], aAddr[0] + aOff + kadd);
            ldsm_x4(af[1], aAddr[1] + aOff + kadd);
            #pragma unroll
            for (int nb = 0; nb < 4; nb++) {
                uint32_t bq[4];
                ldsm_x4(bq, bAddr[nb] + bOff + kadd);
                mma_bf16(acc[0][2 * nb    ], af[0], bq[0], bq[1]);
                mma_bf16(acc[1][2 * nb    ], af[1], bq[0], bq[1]);
                mma_bf16(acc[0][2 * nb + 1], af[0], bq[2], bq[3]);
                mma_bf16(acc[1][2 * nb + 1], af[1], bq[2], bq[3]);
            }
        }
        __syncthreads();

        __half* plane = (__half*)P + (size_t)h * NTOK * NTOK;
        float* rs_h = rsum + h * NTOK;
        #pragma unroll
        for (int mi = 0; mi < 2; mi++) {
            #pragma unroll
            for (int gg = 0; gg < 2; gg++) {
                int r = row0 + wm * 32 + mi * 16 + g + gg * 8;
                float rowacc = 0.f;
                #pragma unroll
                for (int ni = 0; ni < 8; ni++) {
                    int c = col0 + wn * 64 + ni * 8 + tig * 2;
                    float e0 = __expf(0.125f * acc[mi][ni][gg * 2 + 0]);
                    float e1 = __expf(0.125f * acc[mi][ni][gg * 2 + 1]);
                    *(__half2*)(plane + (size_t)r * NTOK + c) = __floats2half2_rn(e0, e1);
                    rowacc += e0 + e1;
                }
                rowacc += __shfl_xor_sync(0xffffffffu, rowacc, 1);
                rowacc += __shfl_xor_sync(0xffffffffu, rowacc, 2);
                if (tig == 0) atomicAdd(&rs_h[r], rowacc);
            }
        }
    }
}

// ================= V transpose (bf16, strided input) =================
__global__ void transpose_v(const unsigned short* __restrict__ V, int ldv,
                            unsigned short* __restrict__ Vt)
{
    __shared__ unsigned short t[32][34];
    int x = blockIdx.x * 32 + threadIdx.x;
    int y0 = blockIdx.y * 32;
    for (int dy = threadIdx.y; dy < 32; dy += 8)
        t[dy][threadIdx.x] = V[(size_t)(y0 + dy) * ldv + x];
    __syncthreads();
    int xo = blockIdx.y * 32 + threadIdx.x;
    int yo0 = blockIdx.x * 32;
    for (int dy = threadIdx.y; dy < 32; dy += 8)
        Vt[(size_t)(yo0 + dy) * NTOK + xo] = t[threadIdx.x][dy];
}

// ================= zero rsum + stats =================
__global__ void zero_kernel(float* __restrict__ rsum)
{
    int i = blockIdx.x * blockDim.x + threadIdx.x;
    if (i < NHEAD * NTOK) rsum[i] = 0.f;
    if (i == 0) { g_stats[0] = 0.0; g_stats[1] = 0.0; }
}

// ================= combine: Wa avg + Gaussian + stats (row-group) =================
__global__ __launch_bounds__(384) void wf_combine_kernel(
    const float* __restrict__ dd, const float* __restrict__ rsum, int row_off)
{
    __shared__ float shInv[NHEAD];
    __shared__ float redA[12], redB[12];
    const int i = row_off + blockIdx.x, tid = threadIdx.x;
    const int lane = tid & 31, wid = tid >> 5;
    const int NP8 = NTOK / 8;
    const size_t PL8 = (size_t)NTOK * NTOK / 8;
    const uint4* planes = (const uint4*)g_Shx;
    const size_t rowoff = (size_t)i * NP8;

    if (tid < NHEAD) shInv[tid] = 1.f / (rsum[tid * NTOK + i] * (float)NHEAD);
    __syncthreads();

    float iz[NHEAD];
    #pragma unroll
    for (int h = 0; h < NHEAD; h++) iz[h] = shInv[h];

    const float4* drow = (const float4*)(dd + (size_t)i * NTOK);
    float4* frow = (float4*)(g_Wf + (size_t)i * NTOK);
    float s1 = 0.f, s2 = 0.f;

    const int j = tid;
    {
        float wa[8];
        #pragma unroll
        for (int q = 0; q < 8; q++) wa[q] = 0.f;
        #pragma unroll
        for (int h = 0; h < NHEAD; h++) {
            uint4 u = planes[h * PL8 + rowoff + j];
            float2 e0 = __half22float2(*(__half2*)&u.x);
            float2 e1 = __half22float2(*(__half2*)&u.y);
            float2 e2 = __half22float2(*(__half2*)&u.z);
            float2 e3 = __half22float2(*(__half2*)&u.w);
            wa[0] += e0.x * iz[h]; wa[1] += e0.y * iz[h];
            wa[2] += e1.x * iz[h]; wa[3] += e1.y * iz[h];
            wa[4] += e2.x * iz[h]; wa[5] += e2.y * iz[h];
            wa[6] += e3.x * iz[h]; wa[7] += e3.y * iz[h];
        }
        float4 d0 = drow[j * 2], d1 = drow[j * 2 + 1];
        float df[8] = {d0.x, d0.y, d0.z, d0.w, d1.x, d1.y, d1.z, d1.w};
        float wf[8];
        #pragma unroll
        for (int q = 0; q < 8; q++) {
            wf[q] = __expf(-0.5f * df[q] * df[q]) * wa[q];
            s1 += wf[q];
            s2 += wf[q] * wf[q];
        }
        float4 w0, w1;
        w0.x = wf[0]; w0.y = wf[1]; w0.z = wf[2]; w0.w = wf[3];
        w1.x = wf[4]; w1.y = wf[5]; w1.z = wf[6]; w1.w = wf[7];
        frow[j * 2] = w0;
        frow[j * 2 + 1] = w1;
    }

    s1 = warp_sum(s1);
    s2 = warp_sum(s2);
    if (lane == 0) { redA[wid] = s1; redB[wid] = s2; }
    __syncthreads();
    if (wid == 0) {
        float a = (lane < 12) ? redA[lane] : 0.f;
        float b = (lane < 12) ? redB[lane] : 0.f;
        a = warp_sum(a);
        b = warp_sum(b);
        if (lane == 0) {
            atomicAdd(&g_stats[0], (double)a);
            atomicAdd(&g_stats[1], (double)b);
        }
    }
}

// ================= masked softmax (no shift) -> bf16 attn =================
__global__ __launch_bounds__(256) void masked_softmax_kernel()
{
    __shared__ float4 z[NTOK / 4];
    __shared__ float redB[8];
    __shared__ float sh_thr;
    const int i = blockIdx.x, tid = threadIdx.x;
    const int lane = tid & 31, wid = tid >> 5;

    if (tid == 0) {
        double cnt = (double)NTOK * (double)NTOK;
        double mean = g_stats[0] / cnt;
        double var = (g_stats[1] - g_stats[0] * g_stats[0] / cnt) / (cnt - 1.0);
        if (var < 0.0) var = 0.0;
        sh_thr = (float)(mean + 0.5 * sqrt(var));
    }
    __syncthreads();
    const float thr = sh_thr;
    const float invthr = 1.f / thr;

    const float4* srow = (const float4*)(g_S + (size_t)i * NTOK);
    const float4* frow = (const float4*)(g_Wf + (size_t)i * NTOK);

    float lsum = 0.f;
    #pragma unroll
    for (int t = 0; t < 3; t++) {
        int j = tid + t * 256;
        float4 wf = frow[j];
        float4 s = srow[j];
        float w0 = (wf.x < thr) ? wf.x * invthr : 1.f;
        float w1 = (wf.y < thr) ? wf.y * invthr : 1.f;
        float w2 = (wf.z < thr) ? wf.z * invthr : 1.f;
        float w3 = (wf.w < thr) ? wf.w * invthr : 1.f;
        float4 e;
        e.x = __expf(s.x * w0);
        e.y = __expf(s.y * w1);
        e.z = __expf(s.z * w2);
        e.w = __expf(s.w * w3);
        z[j] = e;
        lsum += e.x + e.y + e.z + e.w;
    }
    lsum = warp_sum(lsum);
    if (lane == 0) redB[wid] = lsum;
    __syncthreads();
    if (wid == 0) {
        float t = (lane < 8) ? redB[lane] : 0.f;
        t = warp_sum(t);
        if (lane == 0) redB[0] = t;
    }
    __syncthreads();
    const float invs = 1.f / redB[0];

    uint2* arow = (uint2*)((unsigned short*)g_Att + (size_t)i * NTOK);
    #pragma unroll
    for (int t = 0; t < 3; t++) {
        int j = tid + t * 256;
        float4 e = z[j];
        __nv_bfloat162 b0 = __float22bfloat162_rn(make_float2(e.x * invs, e.y * invs));
        __nv_bfloat162 b1 = __float22bfloat162_rn(make_float2(e.z * invs, e.w * invs));
        uint2 u; u.x = *(uint32_t*)&b0; u.y = *(uint32_t*)&b1;
        arow[j] = u;
    }
}

// ================= residual + LayerNorm =================
__global__ __launch_bounds__(256) void ln_kernel(
    const float* __restrict__ hs,
    const float* __restrict__ gamma,
    const float* __restrict__ beta,
    float* __restrict__ out)
{
    const int i = blockIdx.x, tid = threadIdx.x;
    const int lane = tid & 31, wid = tid >> 5;
    __shared__ float r1[8], r2[8];

    const float* orow = g_O + (size_t)i * DIM;
    const float* srow = hs + (size_t)i * DIM;

    float x[3];
    float s = 0.f, ss = 0.f;
    #pragma unroll
    for (int t = 0; t < 3; t++) {
        int c = tid + t * 256;
        x[t] = srow[c] + orow[c];
        s += x[t];
        ss += x[t] * x[t];
    }
    s = warp_sum(s);
    ss = warp_sum(ss);
    if (lane == 0) { r1[wid] = s; r2[wid] = ss; }
    __syncthreads();
    if (wid == 0) {
        float a = (lane < 8) ? r1[lane] : 0.f;
        float b = (lane < 8) ? r2[lane] : 0.f;
        a = warp_sum(a);
        b = warp_sum(b);
        if (lane == 0) { r1[0] = a; r2[0] = b; }
    }
    __syncthreads();
    const float mu = r1[0] * (1.f / DIM);
    const float var = r2[0] * (1.f / DIM) - mu * mu;
    const float inv = rsqrtf(var + 1e-5f);

    #pragma unroll
    for (int t = 0; t < 3; t++) {
        int c = tid + t * 256;
        out[(size_t)i * DIM + c] = (x[t] - mu) * inv * gamma[c] + beta[c];
    }
}

// ================= host =================
extern "C" void kernel_launch(void* const* d_in, const int* in_sizes, int n_in,
                              void* d_out, int out_size)
{
    const float* h_a  = (const float*)d_in[0];
    const float* h_s  = (const float*)d_in[1];
    const float* dep  = (const float*)d_in[2];
    const float* Wq_a = (const float*)d_in[3];
    const float* bq_a = (const float*)d_in[4];
    const float* Wk_a = (const float*)d_in[5];
    const float* bk_a = (const float*)d_in[6];
    const float* Wq   = (const float*)d_in[7];
    const float* bq   = (const float*)d_in[8];
    const float* Wk   = (const float*)d_in[9];
    const float* bk   = (const float*)d_in[10];
    const float* Wv   = (const float*)d_in[11];
    const float* bv   = (const float*)d_in[12];
    const float* lng  = (const float*)d_in[13];
    const float* lnb  = (const float*)d_in[14];
    float* out = (float*)d_out;

    unsigned short *hab, *hsb, *Wca, *Wcb, *qka, *QKV, *Vt, *Att, *Shx;
    float *bca, *bcb, *O, *S, *Wf, *rsum;
    cudaGetSymbolAddress((void**)&hab,  g_hab);
    cudaGetSymbolAddress((void**)&hsb,  g_hsb);
    cudaGetSymbolAddress((void**)&Wca,  g_Wca);
    cudaGetSymbolAddress((void**)&Wcb,  g_Wcb);
    cudaGetSymbolAddress((void**)&bca,  g_bca);
    cudaGetSymbolAddress((void**)&bcb,  g_bcb);
    cudaGetSymbolAddress((void**)&qka,  g_qka);
    cudaGetSymbolAddress((void**)&QKV,  g_QKV);
    cudaGetSymbolAddress((void**)&Vt,   g_Vt);
    cudaGetSymbolAddress((void**)&Att,  g_Att);
    cudaGetSymbolAddress((void**)&Shx,  g_Shx);
    cudaGetSymbolAddress((void**)&O,    g_O);
    cudaGetSymbolAddress((void**)&S,    g_S);
    cudaGetSymbolAddress((void**)&Wf,   g_Wf);
    cudaGetSymbolAddress((void**)&rsum, g_rsum);

    const int SM128 = NSTAGE * (128 * RSTR) * 2;               // 110592
    const int SM64  = NSTAGE * (64 * RSTR + 128 * RSTR);       // 82944

    static cudaStream_t s1, s2;
    static cudaEvent_t e0, e1, eg[4];
    static int inited = 0;
    if (!inited) {
        cudaStreamCreateWithFlags(&s1, cudaStreamNonBlocking);
        cudaStreamCreateWithFlags(&s2, cudaStreamNonBlocking);
        cudaEventCreateWithFlags(&e0, cudaEventDisableTiming);
        cudaEventCreateWithFlags(&e1, cudaEventDisableTiming);
        for (int i = 0; i < 4; i++) cudaEventCreateWithFlags(&eg[i], cudaEventDisableTiming);
        cudaFuncSetAttribute(gemm_nt_bf<64, unsigned short>,
                             cudaFuncAttributeMaxDynamicSharedMemorySize, SM64);
        cudaFuncSetAttribute(gemm_nt_bf<128, float>,
                             cudaFuncAttributeMaxDynamicSharedMemorySize, SM128);
        cudaFuncSetAttribute(gemm_nt_bf<64, float>,
                             cudaFuncAttributeMaxDynamicSharedMemorySize, SM64);
        cudaFuncSetAttribute(heads_gemm_bf,
                             cudaFuncAttributeMaxDynamicSharedMemorySize, SM128);
        inited = 1;
    }

    const dim3 blk(256);
    const dim3 gProjA(2 * DIM / 128, NTOK / 64);   // 12 x 48: qa|ka fused
    const dim3 gProjB(3 * DIM / 128, NTOK / 64);   // 18 x 48: Q|K|V fused
    const dim3 gNN(NTOK / 128, NTOK / 128);        // 24 x 24 (scores)
    const dim3 gHeadsGrp(NTOK / 128, 6);           // 24 x 6 per row-group
    const dim3 gAV(DIM / 128, NTOK / 64);          // 6 x 48
    const int NH4 = (NTOK * DIM) / 4;
    const int NW4 = (DIM * DIM) / 4;

    // biases concat before fork (used by both chains)
    bcat_kernel<<<3, 256>>>(bq_a, bk_a, bca, bq, bk, bv, bcb);

    cudaEventRecord(e0, 0);
    cudaStreamWaitEvent(s1, e0, 0);
    cudaStreamWaitEvent(s2, e0, 0);

    // ---- chain A (s1): structural attention weights ----
    zero_kernel<<<(NHEAD * NTOK + 255) / 256, 256, 0, s1>>>(rsum);
    f2b_multi<<<(NH4 + 2 * NW4 + 255) / 256, 256, 0, s1>>>(
        (const float4*)h_a, (uint2*)hab, NH4,
        (const float4*)Wq_a, (uint2*)Wca, NW4,
        (const float4*)Wk_a, (uint2*)(Wca + DIM * DIM), NW4,
        nullptr, nullptr, 0);
    gemm_nt_bf<64, unsigned short><<<gProjA, blk, SM64, s1>>>(
        hab, DIM, Wca, DIM, qka, 2 * DIM, DIM, bca, 1.f);
    // heads in 4 row-groups on s1; combine per group on s2 overlaps the NEXT heads group
    for (int gp = 0; gp < 4; gp++) {
        heads_gemm_bf<<<gHeadsGrp, blk, SM128, s1>>>(
            qka, 2 * DIM, qka + DIM, 2 * DIM, Shx, rsum, gp * 6);
        cudaEventRecord(eg[gp], s1);
    }
    for (int gp = 0; gp < 4; gp++) {
        cudaStreamWaitEvent(s2, eg[gp], 0);
        wf_combine_kernel<<<768, 384, 0, s2>>>(dep, rsum, gp * 768);
    }
    cudaEventRecord(e1, s2);

    // ---- chain B (default): guided attention ----
    f2b_multi<<<(NH4 + 3 * NW4 + 255) / 256, 256>>>(
        (const float4*)h_s, (uint2*)hsb, NH4,
        (const float4*)Wq, (uint2*)Wcb, NW4,
        (const float4*)Wk, (uint2*)(Wcb + DIM * DIM), NW4,
        (const float4*)Wv, (uint2*)(Wcb + 2 * DIM * DIM), NW4);
    gemm_nt_bf<64, unsigned short><<<gProjB, blk, SM64>>>(
        hsb, DIM, Wcb, DIM, QKV, 3 * DIM, DIM, bcb, 1.f);
    transpose_v<<<dim3(DIM / 32, NTOK / 32), dim3(32, 8)>>>(QKV + 2 * DIM, 3 * DIM, Vt);
    const float score_scale = 1.f / sqrtf((float)DIM);
    gemm_nt_bf<128, float><<<gNN, blk, SM128>>>(
        QKV, 3 * DIM, QKV + DIM, 3 * DIM, S, NTOK, DIM, nullptr, score_scale);

    // join, then tail
    cudaStreamWaitEvent(0, e1, 0);
    masked_softmax_kernel<<<NTOK, 256>>>();
    gemm_nt_bf<64, float><<<gAV, blk, SM64>>>(Att, NTOK, Vt, NTOK, O, DIM, NTOK, nullptr, 1.f);
    ln_kernel<<<NTOK, 256>>>(h_s, lng, lnb, out);
}

// round 15
// speedup vs baseline: 1.0869x; 1.0564x over previous
#include <cuda_runtime.h>
#include <cuda_fp16.h>
#include <cuda_bf16.h>
#include <math.h>
#include <stdint.h>

#define NTOK 3072
#define DIM  768
#define NHEAD 12
#define HDIM 64

// ---------------- static device scratch ----------------
__device__ unsigned short g_hab[NTOK * DIM];
__device__ unsigned short g_hsb[NTOK * DIM];
__device__ unsigned short g_Wca[2 * DIM * DIM];     // Wq_a | Wk_a  bf16
__device__ unsigned short g_Wcb[3 * DIM * DIM];     // Wq | Wk | Wv bf16
__device__ float g_bca[2 * DIM];
__device__ float g_bcb[3 * DIM];
__device__ unsigned short g_qka[NTOK * 2 * DIM];    // qa | ka bf16 (ld 1536)
__device__ unsigned short g_QKV[NTOK * 3 * DIM];    // Q | K | V bf16 (ld 2304)
__device__ unsigned short g_Vt [DIM * NTOK];        // V^T bf16
__device__ float g_O [NTOK * DIM];
__device__ float g_S [(size_t)NTOK * NTOK];
__device__ unsigned short g_Att[(size_t)NTOK * NTOK];
__device__ unsigned short g_Shx[(size_t)NHEAD * NTOK * NTOK]; // fp16 exp planes
__device__ float g_Wf[(size_t)NTOK * NTOK];
__device__ float g_rsum[NHEAD * NTOK];
__device__ double g_stats[2];

// ---------------- helpers ----------------
__device__ __forceinline__ float warp_sum(float v) {
    #pragma unroll
    for (int o = 16; o; o >>= 1) v += __shfl_xor_sync(0xffffffffu, v, o);
    return v;
}
__device__ __forceinline__ void mma_bf16(float* d, const uint32_t* a, uint32_t b0, uint32_t b1) {
    asm volatile(
        "mma.sync.aligned.m16n8k16.row.col.f32.bf16.bf16.f32 "
        "{%0,%1,%2,%3}, {%4,%5,%6,%7}, {%8,%9}, {%0,%1,%2,%3};\n"
        : "+f"(d[0]), "+f"(d[1]), "+f"(d[2]), "+f"(d[3])
        : "r"(a[0]), "r"(a[1]), "r"(a[2]), "r"(a[3]), "r"(b0), "r"(b1));
}
__device__ __forceinline__ void ldsm_x4(uint32_t* r, uint32_t addr) {
    asm volatile("ldmatrix.sync.aligned.m8n8.x4.shared.b16 {%0,%1,%2,%3}, [%4];"
        : "=r"(r[0]), "=r"(r[1]), "=r"(r[2]), "=r"(r[3]) : "r"(addr));
}
__device__ __forceinline__ void cpa16(uint32_t smem, const void* gptr) {
    asm volatile("cp.async.ca.shared.global [%0], [%1], 16;\n" :: "r"(smem), "l"(gptr));
}
#define CP_COMMIT()  asm volatile("cp.async.commit_group;\n")
#define CP_WAIT(N)   asm volatile("cp.async.wait_group %0;\n" :: "n"(N))

#define RSTR 144        // bytes per smem row (128 data + 16 pad); conflict-free
#define NSTAGE 3

// ---------------- fp32 -> bf16 conversion, multi-array fused ----------------
__global__ void f2b_multi(const float4* a0, uint2* o0, int n0,
                          const float4* a1, uint2* o1, int n1,
                          const float4* a2, uint2* o2, int n2,
                          const float4* a3, uint2* o3, int n3)
{
    int i = blockIdx.x * blockDim.x + threadIdx.x;
    const float4* in; uint2* out; int idx;
    if (i < n0) { in = a0; out = o0; idx = i; }
    else if (i < n0 + n1) { in = a1; out = o1; idx = i - n0; }
    else if (i < n0 + n1 + n2) { in = a2; out = o2; idx = i - n0 - n1; }
    else if (i < n0 + n1 + n2 + n3) { in = a3; out = o3; idx = i - n0 - n1 - n2; }
    else return;
    float4 v = in[idx];
    __nv_bfloat162 a = __float22bfloat162_rn(make_float2(v.x, v.y));
    __nv_bfloat162 b = __float22bfloat162_rn(make_float2(v.z, v.w));
    uint2 u; u.x = *(uint32_t*)&a; u.y = *(uint32_t*)&b;
    out[idx] = u;
}

// ---------------- bias concat ----------------
__global__ void bcat_kernel(const float* a0, const float* a1, float* outA,
                            const float* b0, const float* b1, const float* b2, float* outB)
{
    int i = blockIdx.x * blockDim.x + threadIdx.x;
    if (i < DIM) {
        outA[i] = a0[i]; outA[DIM + i] = a1[i];
        outB[i] = b0[i]; outB[DIM + i] = b1[i]; outB[2 * DIM + i] = b2[i];
    }
}

// ================= bf16 TC NT GEMM (ldmatrix, BK=64, 3-stage): C = scale*A.B^T (+bias) =================
template <int BM, typename OutT>
__global__ __launch_bounds__(256, 2) void gemm_nt_bf(
    const unsigned short* __restrict__ A, int lda,
    const unsigned short* __restrict__ B, int ldb,
    OutT* __restrict__ C, int ldc, int K,
    const float* __restrict__ bias, float scale)
{
    constexpr int WMN = BM / 32;
    constexpr int WNN = 8 / WMN;
    constexpr int NI  = 128 / (WNN * 8);
    constexpr int NB  = NI / 2;
    constexpr int CA  = BM / 32;
    constexpr int CB  = 4;
    constexpr uint32_t stgA = BM * RSTR;
    constexpr uint32_t stgB = 128 * RSTR;

    extern __shared__ uint32_t dynsm[];
    const uint32_t sbase = (uint32_t)__cvta_generic_to_shared(dynsm);
    const uint32_t sA = sbase;
    const uint32_t sB = sbase + NSTAGE * stgA;

    const int tid = threadIdx.x;
    const int row0 = blockIdx.y * BM, col0 = blockIdx.x * 128;
    const int wid = tid >> 5, lane = tid & 31;
    const int wm = wid % WMN, wn = wid / WMN;
    const int g = lane >> 2, tig = lane & 3;
    const int seg = lane >> 3, l7 = lane & 7;

    float acc[2][NI][4];
    #pragma unroll
    for (int i = 0; i < 2; i++)
        #pragma unroll
        for (int j = 0; j < NI; j++)
            #pragma unroll
            for (int q = 0; q < 4; q++) acc[i][j][q] = 0.f;

    const unsigned short* gA[CA]; uint32_t dA[CA];
    #pragma unroll
    for (int t = 0; t < CA; t++) {
        int ch = tid + t * 256;
        int r = ch >> 3, c16 = ch & 7;
        gA[t] = A + (size_t)(row0 + r) * lda + c16 * 8;
        dA[t] = sA + r * RSTR + c16 * 16;
    }
    const unsigned short* gB[CB]; uint32_t dB[CB];
    #pragma unroll
    for (int t = 0; t < CB; t++) {
        int ch = tid + t * 256;
        int r = ch >> 3, c16 = ch & 7;
        gB[t] = B + (size_t)(col0 + r) * ldb + c16 * 8;
        dB[t] = sB + r * RSTR + c16 * 16;
    }

    const int rowA = (seg & 1) * 8 + l7;
    const uint32_t kAb = (seg >> 1) * 16;
    uint32_t aAddr[2];
    #pragma unroll
    for (int mi = 0; mi < 2; mi++)
        aAddr[mi] = sA + (uint32_t)(wm * 32 + mi * 16 + rowA) * RSTR + kAb;
    const int rowB = (seg >> 1) * 8 + l7;
    const uint32_t kBb = (seg & 1) * 16;
    uint32_t bAddr[NB];
    #pragma unroll
    for (int nb = 0; nb < NB; nb++)
        bAddr[nb] = sB + (uint32_t)(wn * (NI * 8) + nb * 16 + rowB) * RSTR + kBb;

    const int niter = K >> 6;

    #pragma unroll
    for (int s = 0; s < 2; s++) {
        const int k0 = s << 6;
        #pragma unroll
        for (int t = 0; t < CA; t++) cpa16(dA[t] + s * stgA, gA[t] + k0);
        #pragma unroll
        for (int t = 0; t < CB; t++) cpa16(dB[t] + s * stgB, gB[t] + k0);
        CP_COMMIT();
    }

    for (int it = 0; it < niter; ++it) {
        if (it + 2 < niter) {
            const int s = (it + 2) % NSTAGE;
            const int k0 = (it + 2) << 6;
            #pragma unroll
            for (int t = 0; t < CA; t++) cpa16(dA[t] + s * stgA, gA[t] + k0);
            #pragma unroll
            for (int t = 0; t < CB; t++) cpa16(dB[t] + s * stgB, gB[t] + k0);
            CP_COMMIT();
            CP_WAIT(2);
        } else if (it + 2 == niter) {
            CP_WAIT(1);
        } else {
            CP_WAIT(0);
        }
        __syncthreads();

        const int st = it % NSTAGE;
        const uint32_t aOff = st * stgA, bOff = st * stgB;
        #pragma unroll
        for (int ks = 0; ks < 4; ks++) {
            const uint32_t kadd = ks * 32;
            uint32_t af[2][4];
            ldsm_x4(af[0], aAddr[0] + aOff + kadd);
            ldsm_x4(af[1], aAddr[1] + aOff + kadd);
            #pragma unroll
            for (int nb = 0; nb < NB; nb++) {
                uint32_t bq[4];
                ldsm_x4(bq, bAddr[nb] + bOff + kadd);
                mma_bf16(acc[0][2 * nb    ], af[0], bq[0], bq[1]);
                mma_bf16(acc[1][2 * nb    ], af[1], bq[0], bq[1]);
                mma_bf16(acc[0][2 * nb + 1], af[0], bq[2], bq[3]);
                mma_bf16(acc[1][2 * nb + 1], af[1], bq[2], bq[3]);
            }
        }
        __syncthreads();
    }

    #pragma unroll
    for (int mi = 0; mi < 2; mi++) {
        #pragma unroll
        for (int gg = 0; gg < 2; gg++) {
            int r = row0 + wm * 32 + mi * 16 + g + gg * 8;
            #pragma unroll
            for (int ni = 0; ni < NI; ni++) {
                int c = col0 + wn * (NI * 8) + ni * 8 + tig * 2;
                float vx = acc[mi][ni][gg * 2 + 0] * scale;
                float vy = acc[mi][ni][gg * 2 + 1] * scale;
                if (bias) { vx += bias[c]; vy += bias[c + 1]; }
                if constexpr (sizeof(OutT) == 2) {
                    __nv_bfloat162 bv = __float22bfloat162_rn(make_float2(vx, vy));
                    *(uint32_t*)((unsigned short*)C + (size_t)r * ldc + c) = *(uint32_t*)&bv;
                } else {
                    float2 v; v.x = vx; v.y = vy;
                    *(float2*)((float*)C + (size_t)r * ldc + c) = v;
                }
            }
        }
    }
}

// ================= fused 12-head logits GEMM (BK=64: 1 stage per head) =================
// Epilogue: exp(logit/8) -> fp16 plane via quad-shuffle 16B vectorized stores + row sums.
__global__ __launch_bounds__(256, 2) void heads_gemm_bf(
    const unsigned short* __restrict__ A, int lda,
    const unsigned short* __restrict__ B, int ldb,
    unsigned short* __restrict__ P,
    float* __restrict__ rsum)
{
    constexpr uint32_t stgA = 128 * RSTR;
    constexpr uint32_t stgB = 128 * RSTR;

    extern __shared__ uint32_t dynsm[];
    const uint32_t sbase = (uint32_t)__cvta_generic_to_shared(dynsm);
    const uint32_t sA = sbase;
    const uint32_t sB = sbase + NSTAGE * stgA;

    const int tid = threadIdx.x;
    const int row0 = blockIdx.y * 128, col0 = blockIdx.x * 128;
    const int wid = tid >> 5, lane = tid & 31;
    const int wm = wid & 3, wn = wid >> 2;
    const int g = lane >> 2, tig = lane & 3;
    const int seg = lane >> 3, l7 = lane & 7;
    const int qbase = lane & ~3;   // first lane of this quad

    const unsigned short* gA[4]; uint32_t dA[4];
    const unsigned short* gB[4]; uint32_t dB[4];
    #pragma unroll
    for (int t = 0; t < 4; t++) {
        int ch = tid + t * 256;
        int r = ch >> 3, c16 = ch & 7;
        gA[t] = A + (size_t)(row0 + r) * lda + c16 * 8;
        dA[t] = sA + r * RSTR + c16 * 16;
        gB[t] = B + (size_t)(col0 + r) * ldb + c16 * 8;
        dB[t] = sB + r * RSTR + c16 * 16;
    }

    const int rowA = (seg & 1) * 8 + l7;
    const uint32_t kAb = (seg >> 1) * 16;
    uint32_t aAddr[2];
    #pragma unroll
    for (int mi = 0; mi < 2; mi++)
        aAddr[mi] = sA + (uint32_t)(wm * 32 + mi * 16 + rowA) * RSTR + kAb;
    const int rowB = (seg >> 1) * 8 + l7;
    const uint32_t kBb = (seg & 1) * 16;
    uint32_t bAddr[4];
    #pragma unroll
    for (int nb = 0; nb < 4; nb++)
        bAddr[nb] = sB + (uint32_t)(wn * 64 + nb * 16 + rowB) * RSTR + kBb;

    #pragma unroll
    for (int s = 0; s < 2; s++) {
        const int k0 = s << 6;
        #pragma unroll
        for (int t = 0; t < 4; t++) {
            cpa16(dA[t] + s * stgA, gA[t] + k0);
            cpa16(dB[t] + s * stgB, gB[t] + k0);
        }
        CP_COMMIT();
    }

    for (int h = 0; h < NHEAD; h++) {
        if (h + 2 < NHEAD) {
            const int s = (h + 2) % NSTAGE;
            const int k0 = (h + 2) << 6;
            #pragma unroll
            for (int t = 0; t < 4; t++) {
                cpa16(dA[t] + s * stgA, gA[t] + k0);
                cpa16(dB[t] + s * stgB, gB[t] + k0);
            }
            CP_COMMIT();
            CP_WAIT(2);
        } else if (h + 2 == NHEAD) {
            CP_WAIT(1);
        } else {
            CP_WAIT(0);
        }
        __syncthreads();

        float acc[2][8][4];
        #pragma unroll
        for (int i = 0; i < 2; i++)
            #pragma unroll
            for (int j = 0; j < 8; j++)
                #pragma unroll
                for (int q = 0; q < 4; q++) acc[i][j][q] = 0.f;

        const int st = h % NSTAGE;
        const uint32_t aOff = st * stgA, bOff = st * stgB;
        #pragma unroll
        for (int ks = 0; ks < 4; ks++) {
            const uint32_t kadd = ks * 32;
            uint32_t af[2][4];
            ldsm_x4(af[0], aAddr[0] + aOff + kadd);
            ldsm_x4(af[1], aAddr[1] + aOff + kadd);
            #pragma unroll
            for (int nb = 0; nb < 4; nb++) {
                uint32_t bq[4];
                ldsm_x4(bq, bAddr[nb] + bOff + kadd);
                mma_bf16(acc[0][2 * nb    ], af[0], bq[0], bq[1]);
                mma_bf16(acc[1][2 * nb    ], af[1], bq[0], bq[1]);
                mma_bf16(acc[0][2 * nb + 1], af[0], bq[2], bq[3]);
                mma_bf16(acc[1][2 * nb + 1], af[1], bq[2], bq[3]);
            }
        }
        __syncthreads();

        __half* plane = (__half*)P + (size_t)h * NTOK * NTOK;
        float* rs_h = rsum + h * NTOK;
        #pragma unroll
        for (int mi = 0; mi < 2; mi++) {
            #pragma unroll
            for (int gg = 0; gg < 2; gg++) {
                int r = row0 + wm * 32 + mi * 16 + g + gg * 8;
                float rowacc = 0.f;
                uint32_t pk[8];
                #pragma unroll
                for (int ni = 0; ni < 8; ni++) {
                    float e0 = __expf(0.125f * acc[mi][ni][gg * 2 + 0]);
                    float e1 = __expf(0.125f * acc[mi][ni][gg * 2 + 1]);
                    __half2 hh = __floats2half2_rn(e0, e1);
                    pk[ni] = *(uint32_t*)&hh;
                    rowacc += e0 + e1;
                }
                // quad-shuffle gather: chunk n covers cols [n*8, n*8+8) of this warp's
                // 64-col span; its 4 half2 live in tig lanes 0..3 (uniform indices).
                uint4 u0, u1;
                #pragma unroll
                for (int n = 0; n < 8; n++) {
                    uint32_t x = __shfl_sync(0xffffffffu, pk[n], qbase + 0);
                    uint32_t y = __shfl_sync(0xffffffffu, pk[n], qbase + 1);
                    uint32_t z = __shfl_sync(0xffffffffu, pk[n], qbase + 2);
                    uint32_t w = __shfl_sync(0xffffffffu, pk[n], qbase + 3);
                    if (tig == (n >> 1)) {
                        if ((n & 1) == 0) { u0.x = x; u0.y = y; u0.z = z; u0.w = w; }
                        else              { u1.x = x; u1.y = y; u1.z = z; u1.w = w; }
                    }
                }
                __half* base = plane + (size_t)r * NTOK + col0 + wn * 64;
                *(uint4*)(base + (2 * tig    ) * 8) = u0;
                *(uint4*)(base + (2 * tig + 1) * 8) = u1;

                rowacc += __shfl_xor_sync(0xffffffffu, rowacc, 1);
                rowacc += __shfl_xor_sync(0xffffffffu, rowacc, 2);
                if (tig == 0) atomicAdd(&rs_h[r], rowacc);
            }
        }
    }
}

// ================= V transpose (bf16, strided input) =================
__global__ void transpose_v(const unsigned short* __restrict__ V, int ldv,
                            unsigned short* __restrict__ Vt)
{
    __shared__ unsigned short t[32][34];
    int x = blockIdx.x * 32 + threadIdx.x;
    int y0 = blockIdx.y * 32;
    for (int dy = threadIdx.y; dy < 32; dy += 8)
        t[dy][threadIdx.x] = V[(size_t)(y0 + dy) * ldv + x];
    __syncthreads();
    int xo = blockIdx.y * 32 + threadIdx.x;
    int yo0 = blockIdx.x * 32;
    for (int dy = threadIdx.y; dy < 32; dy += 8)
        Vt[(size_t)(yo0 + dy) * NTOK + xo] = t[threadIdx.x][dy];
}

// ================= zero rsum + stats =================
__global__ void zero_kernel(float* __restrict__ rsum)
{
    int i = blockIdx.x * blockDim.x + threadIdx.x;
    if (i < NHEAD * NTOK) rsum[i] = 0.f;
    if (i == 0) { g_stats[0] = 0.0; g_stats[1] = 0.0; }
}

// ================= combine: Wa avg + Gaussian + stats =================
__global__ __launch_bounds__(384) void wf_combine_kernel(
    const float* __restrict__ dd, const float* __restrict__ rsum)
{
    __shared__ float shInv[NHEAD];
    __shared__ float redA[12], redB[12];
    const int i = blockIdx.x, tid = threadIdx.x;
    const int lane = tid & 31, wid = tid >> 5;
    const int NP8 = NTOK / 8;
    const size_t PL8 = (size_t)NTOK * NTOK / 8;
    const uint4* planes = (const uint4*)g_Shx;
    const size_t rowoff = (size_t)i * NP8;

    if (tid < NHEAD) shInv[tid] = 1.f / (rsum[tid * NTOK + i] * (float)NHEAD);
    __syncthreads();

    float iz[NHEAD];
    #pragma unroll
    for (int h = 0; h < NHEAD; h++) iz[h] = shInv[h];

    const float4* drow = (const float4*)(dd + (size_t)i * NTOK);
    float4* frow = (float4*)(g_Wf + (size_t)i * NTOK);
    float s1 = 0.f, s2 = 0.f;

    const int j = tid;
    {
        float wa[8];
        #pragma unroll
        for (int q = 0; q < 8; q++) wa[q] = 0.f;
        #pragma unroll
        for (int h = 0; h < NHEAD; h++) {
            uint4 u = planes[h * PL8 + rowoff + j];
            float2 e0 = __half22float2(*(__half2*)&u.x);
            float2 e1 = __half22float2(*(__half2*)&u.y);
            float2 e2 = __half22float2(*(__half2*)&u.z);
            float2 e3 = __half22float2(*(__half2*)&u.w);
            wa[0] += e0.x * iz[h]; wa[1] += e0.y * iz[h];
            wa[2] += e1.x * iz[h]; wa[3] += e1.y * iz[h];
            wa[4] += e2.x * iz[h]; wa[5] += e2.y * iz[h];
            wa[6] += e3.x * iz[h]; wa[7] += e3.y * iz[h];
        }
        float4 d0 = drow[j * 2], d1 = drow[j * 2 + 1];
        float df[8] = {d0.x, d0.y, d0.z, d0.w, d1.x, d1.y, d1.z, d1.w};
        float wf[8];
        #pragma unroll
        for (int q = 0; q < 8; q++) {
            wf[q] = __expf(-0.5f * df[q] * df[q]) * wa[q];
            s1 += wf[q];
            s2 += wf[q] * wf[q];
        }
        float4 w0, w1;
        w0.x = wf[0]; w0.y = wf[1]; w0.z = wf[2]; w0.w = wf[3];
        w1.x = wf[4]; w1.y = wf[5]; w1.z = wf[6]; w1.w = wf[7];
        frow[j * 2] = w0;
        frow[j * 2 + 1] = w1;
    }

    s1 = warp_sum(s1);
    s2 = warp_sum(s2);
    if (lane == 0) { redA[wid] = s1; redB[wid] = s2; }
    __syncthreads();
    if (wid == 0) {
        float a = (lane < 12) ? redA[lane] : 0.f;
        float b = (lane < 12) ? redB[lane] : 0.f;
        a = warp_sum(a);
        b = warp_sum(b);
        if (lane == 0) {
            atomicAdd(&g_stats[0], (double)a);
            atomicAdd(&g_stats[1], (double)b);
        }
    }
}

// ================= masked softmax (no shift) -> bf16 attn =================
__global__ __launch_bounds__(256) void masked_softmax_kernel()
{
    __shared__ float4 z[NTOK / 4];
    __shared__ float redB[8];
    __shared__ float sh_thr;
    const int i = blockIdx.x, tid = threadIdx.x;
    const int lane = tid & 31, wid = tid >> 5;

    if (tid == 0) {
        double cnt = (double)NTOK * (double)NTOK;
        double mean = g_stats[0] / cnt;
        double var = (g_stats[1] - g_stats[0] * g_stats[0] / cnt) / (cnt - 1.0);
        if (var < 0.0) var = 0.0;
        sh_thr = (float)(mean + 0.5 * sqrt(var));
    }
    __syncthreads();
    const float thr = sh_thr;
    const float invthr = 1.f / thr;

    const float4* srow = (const float4*)(g_S + (size_t)i * NTOK);
    const float4* frow = (const float4*)(g_Wf + (size_t)i * NTOK);

    float lsum = 0.f;
    #pragma unroll
    for (int t = 0; t < 3; t++) {
        int j = tid + t * 256;
        float4 wf = frow[j];
        float4 s = srow[j];
        float w0 = (wf.x < thr) ? wf.x * invthr : 1.f;
        float w1 = (wf.y < thr) ? wf.y * invthr : 1.f;
        float w2 = (wf.z < thr) ? wf.z * invthr : 1.f;
        float w3 = (wf.w < thr) ? wf.w * invthr : 1.f;
        float4 e;
        e.x = __expf(s.x * w0);
        e.y = __expf(s.y * w1);
        e.z = __expf(s.z * w2);
        e.w = __expf(s.w * w3);
        z[j] = e;
        lsum += e.x + e.y + e.z + e.w;
    }
    lsum = warp_sum(lsum);
    if (lane == 0) redB[wid] = lsum;
    __syncthreads();
    if (wid == 0) {
        float t = (lane < 8) ? redB[lane] : 0.f;
        t = warp_sum(t);
        if (lane == 0) redB[0] = t;
    }
    __syncthreads();
    const float invs = 1.f / redB[0];

    uint2* arow = (uint2*)((unsigned short*)g_Att + (size_t)i * NTOK);
    #pragma unroll
    for (int t = 0; t < 3; t++) {
        int j = tid + t * 256;
        float4 e = z[j];
        __nv_bfloat162 b0 = __float22bfloat162_rn(make_float2(e.x * invs, e.y * invs));
        __nv_bfloat162 b1 = __float22bfloat162_rn(make_float2(e.z * invs, e.w * invs));
        uint2 u; u.x = *(uint32_t*)&b0; u.y = *(uint32_t*)&b1;
        arow[j] = u;
    }
}

// ================= residual + LayerNorm =================
__global__ __launch_bounds__(256) void ln_kernel(
    const float* __restrict__ hs,
    const float* __restrict__ gamma,
    const float* __restrict__ beta,
    float* __restrict__ out)
{
    const int i = blockIdx.x, tid = threadIdx.x;
    const int lane = tid & 31, wid = tid >> 5;
    __shared__ float r1[8], r2[8];

    const float* orow = g_O + (size_t)i * DIM;
    const float* srow = hs + (size_t)i * DIM;

    float x[3];
    float s = 0.f, ss = 0.f;
    #pragma unroll
    for (int t = 0; t < 3; t++) {
        int c = tid + t * 256;
        x[t] = srow[c] + orow[c];
        s += x[t];
        ss += x[t] * x[t];
    }
    s = warp_sum(s);
    ss = warp_sum(ss);
    if (lane == 0) { r1[wid] = s; r2[wid] = ss; }
    __syncthreads();
    if (wid == 0) {
        float a = (lane < 8) ? r1[lane] : 0.f;
        float b = (lane < 8) ? r2[lane] : 0.f;
        a = warp_sum(a);
        b = warp_sum(b);
        if (lane == 0) { r1[0] = a; r2[0] = b; }
    }
    __syncthreads();
    const float mu = r1[0] * (1.f / DIM);
    const float var = r2[0] * (1.f / DIM) - mu * mu;
    const float inv = rsqrtf(var + 1e-5f);

    #pragma unroll
    for (int t = 0; t < 3; t++) {
        int c = tid + t * 256;
        out[(size_t)i * DIM + c] = (x[t] - mu) * inv * gamma[c] + beta[c];
    }
}

// ================= host =================
extern "C" void kernel_launch(void* const* d_in, const int* in_sizes, int n_in,
                              void* d_out, int out_size)
{
    const float* h_a  = (const float*)d_in[0];
    const float* h_s  = (const float*)d_in[1];
    const float* dep  = (const float*)d_in[2];
    const float* Wq_a = (const float*)d_in[3];
    const float* bq_a = (const float*)d_in[4];
    const float* Wk_a = (const float*)d_in[5];
    const float* bk_a = (const float*)d_in[6];
    const float* Wq   = (const float*)d_in[7];
    const float* bq   = (const float*)d_in[8];
    const float* Wk   = (const float*)d_in[9];
    const float* bk   = (const float*)d_in[10];
    const float* Wv   = (const float*)d_in[11];
    const float* bv   = (const float*)d_in[12];
    const float* lng  = (const float*)d_in[13];
    const float* lnb  = (const float*)d_in[14];
    float* out = (float*)d_out;

    unsigned short *hab, *hsb, *Wca, *Wcb, *qka, *QKV, *Vt, *Att, *Shx;
    float *bca, *bcb, *O, *S, *Wf, *rsum;
    cudaGetSymbolAddress((void**)&hab,  g_hab);
    cudaGetSymbolAddress((void**)&hsb,  g_hsb);
    cudaGetSymbolAddress((void**)&Wca,  g_Wca);
    cudaGetSymbolAddress((void**)&Wcb,  g_Wcb);
    cudaGetSymbolAddress((void**)&bca,  g_bca);
    cudaGetSymbolAddress((void**)&bcb,  g_bcb);
    cudaGetSymbolAddress((void**)&qka,  g_qka);
    cudaGetSymbolAddress((void**)&QKV,  g_QKV);
    cudaGetSymbolAddress((void**)&Vt,   g_Vt);
    cudaGetSymbolAddress((void**)&Att,  g_Att);
    cudaGetSymbolAddress((void**)&Shx,  g_Shx);
    cudaGetSymbolAddress((void**)&O,    g_O);
    cudaGetSymbolAddress((void**)&S,    g_S);
    cudaGetSymbolAddress((void**)&Wf,   g_Wf);
    cudaGetSymbolAddress((void**)&rsum, g_rsum);

    const int SM128 = NSTAGE * (128 * RSTR) * 2;               // 110592
    const int SM64  = NSTAGE * (64 * RSTR + 128 * RSTR);       // 82944

    static cudaStream_t s1;
    static cudaEvent_t e0, e1;
    static int inited = 0;
    if (!inited) {
        cudaStreamCreateWithFlags(&s1, cudaStreamNonBlocking);
        cudaEventCreateWithFlags(&e0, cudaEventDisableTiming);
        cudaEventCreateWithFlags(&e1, cudaEventDisableTiming);
        cudaFuncSetAttribute(gemm_nt_bf<64, unsigned short>,
                             cudaFuncAttributeMaxDynamicSharedMemorySize, SM64);
        cudaFuncSetAttribute(gemm_nt_bf<128, float>,
                             cudaFuncAttributeMaxDynamicSharedMemorySize, SM128);
        cudaFuncSetAttribute(gemm_nt_bf<64, float>,
                             cudaFuncAttributeMaxDynamicSharedMemorySize, SM64);
        cudaFuncSetAttribute(heads_gemm_bf,
                             cudaFuncAttributeMaxDynamicSharedMemorySize, SM128);
        inited = 1;
    }

    const dim3 blk(256);
    const dim3 gProjA(2 * DIM / 128, NTOK / 64);   // 12 x 48: qa|ka fused
    const dim3 gProjB(3 * DIM / 128, NTOK / 64);   // 18 x 48: Q|K|V fused
    const dim3 gNN(NTOK / 128, NTOK / 128);        // 24 x 24
    const dim3 gAV(DIM / 128, NTOK / 64);          // 6 x 48
    const int NH4 = (NTOK * DIM) / 4;
    const int NW4 = (DIM * DIM) / 4;

    // biases concat before fork (used by both chains)
    bcat_kernel<<<3, 256>>>(bq_a, bk_a, bca, bq, bk, bv, bcb);

    cudaEventRecord(e0, 0);
    cudaStreamWaitEvent(s1, e0, 0);

    // ---- chain A (s1): structural attention weights ----
    zero_kernel<<<(NHEAD * NTOK + 255) / 256, 256, 0, s1>>>(rsum);
    f2b_multi<<<(NH4 + 2 * NW4 + 255) / 256, 256, 0, s1>>>(
        (const float4*)h_a, (uint2*)hab, NH4,
        (const float4*)Wq_a, (uint2*)Wca, NW4,
        (const float4*)Wk_a, (uint2*)(Wca + DIM * DIM), NW4,
        nullptr, nullptr, 0);
    gemm_nt_bf<64, unsigned short><<<gProjA, blk, SM64, s1>>>(
        hab, DIM, Wca, DIM, qka, 2 * DIM, DIM, bca, 1.f);
    heads_gemm_bf<<<gNN, blk, SM128, s1>>>(qka, 2 * DIM, qka + DIM, 2 * DIM, Shx, rsum);
    wf_combine_kernel<<<NTOK, 384, 0, s1>>>(dep, rsum);
    cudaEventRecord(e1, s1);

    // ---- chain B (default): guided attention ----
    f2b_multi<<<(NH4 + 3 * NW4 + 255) / 256, 256>>>(
        (const float4*)h_s, (uint2*)hsb, NH4,
        (const float4*)Wq, (uint2*)Wcb, NW4,
        (const float4*)Wk, (uint2*)(Wcb + DIM * DIM), NW4,
        (const float4*)Wv, (uint2*)(Wcb + 2 * DIM * DIM), NW4);
    gemm_nt_bf<64, unsigned short><<<gProjB, blk, SM64>>>(
        hsb, DIM, Wcb, DIM, QKV, 3 * DIM, DIM, bcb, 1.f);
    transpose_v<<<dim3(DIM / 32, NTOK / 32), dim3(32, 8)>>>(QKV + 2 * DIM, 3 * DIM, Vt);
    const float score_scale = 1.f / sqrtf((float)DIM);
    gemm_nt_bf<128, float><<<gNN, blk, SM128>>>(
        QKV, 3 * DIM, QKV + DIM, 3 * DIM, S, NTOK, DIM, nullptr, score_scale);

    // join, then tail
    cudaStreamWaitEvent(0, e1, 0);
    masked_softmax_kernel<<<NTOK, 256>>>();
    gemm_nt_bf<64, float><<<gAV, blk, SM64>>>(Att, NTOK, Vt, NTOK, O, DIM, NTOK, nullptr, 1.f);
    ln_kernel<<<NTOK, 256>>>(h_s, lng, lnb, out);
}